// round 8
// baseline (speedup 1.0000x reference)
#include <cuda_runtime.h>
#include <cuda_fp16.h>
#include <cstddef>
#include <cstdint>

#define N_VARS   4096
#define WIDTH    8192
#define N_LAYERS 12
#define BATCH    1024
#define THREADS  1024
#define BCH      8
#define NPT      (WIDTH / THREADS)          // 8
#define NPRE     4
#define N_PAIRS  (N_LAYERS / 2)             // 6 fused stages
#define SLOTS    (WIDTH / 8)                // 1024 positions per residue class

typedef unsigned int u32;

// ---------------- device-global scratch (sanctioned) ----------------
__device__ int4 g_fused [N_PAIRS * WIDTH];   // original fused tables
__device__ int4 g_fused2[N_PAIRS * WIDTH];   // permuted + remapped tables
__device__ int  g_res  [N_PAIRS * WIDTH];    // 64-way class (c1*8 | rotated c2)
__device__ int  g_bh   [N_PAIRS][8][64];     // per-block class histograms
__device__ int  g_bb   [N_PAIRS][8][64];     // per-block exclusive bases
__device__ int  g_S    [N_PAIRS][64];        // within-c1 prefix of 64-class sizes
__device__ int  g_szc1 [N_PAIRS][8];         // c1 class sizes
__device__ int  g_ovfb [N_PAIRS][8];         // overflow base per c1
__device__ int  g_pos  [N_PAIRS * WIDTH];    // node -> position
__device__ int  g_inv  [N_PAIRS * WIDTH];    // position -> node

// ---------------- K1: build fused tables + residue classes + block hist ----
// stage p fuses layers (2p, 2p+1):
//   s = ch[2p+1][n]; (A,B) = ch[2p][s.x]; (C,D) = ch[2p][s.y]
// First-gather residue chain: r=n; for q=p..0: r = ch[2q][ch[2q+1][r].x].x
// Second-gather chain: one .y hop at level p, then .x chains below.
__global__ __launch_bounds__(1024) void k1_fuse_res(const int2* __restrict__ ch)
{
    const int p = blockIdx.x >> 3;
    const int n = ((blockIdx.x & 7) << 10) + threadIdx.x;
    __shared__ int hist[64];
    if (threadIdx.x < 64) hist[threadIdx.x] = 0;
    __syncthreads();

    // fused table entry
    const int2 s = __ldg(&ch[(size_t)(2 * p + 1) * WIDTH + n]);
    const int2 a = __ldg(&ch[(size_t)(2 * p) * WIDTH + s.x]);
    const int2 b = __ldg(&ch[(size_t)(2 * p) * WIDTH + s.y]);
    g_fused[(size_t)p * WIDTH + n] = make_int4(a.x, a.y, b.x, b.y);

    // c1 chain (first child all the way down)
    int r = n;
    for (int q = p; q >= 0; --q) {
        int sx = __ldg(&ch[(size_t)(2 * q + 1) * WIDTH + r]).x;
        r = __ldg(&ch[(size_t)(2 * q) * WIDTH + sx]).x;
    }
    const int c1 = r & 7;

    // c2 chain (second child at level p, first-child chains below)
    int r2 = a.y;                           // comp2 index into stage p-1 (or input if p==0)
    for (int q = p - 1; q >= 0; --q) {
        int sx = __ldg(&ch[(size_t)(2 * q + 1) * WIDTH + r2]).x;
        r2 = __ldg(&ch[(size_t)(2 * q) * WIDTH + sx]).x;
    }
    const int c2 = r2 & 7;

    const int cls = (c1 << 3) | ((c2 - c1) & 7);   // rotated second key
    g_res[(size_t)p * WIDTH + n] = cls;

    // deterministic block histogram (totals only)
    unsigned mask = __match_any_sync(0xffffffffu, cls);
    if ((__ffs(mask) - 1) == (int)(threadIdx.x & 31))
        atomicAdd(&hist[cls], __popc(mask));
    __syncthreads();
    if (threadIdx.x < 64)
        g_bh[p][blockIdx.x & 7][threadIdx.x] = hist[threadIdx.x];
}

// ---------------- K2: per-stage scans (6 blocks x 64 threads) -------------
__global__ __launch_bounds__(64) void k2_scan()
{
    const int p = blockIdx.x;
    const int c = threadIdx.x;              // 64-way class
    __shared__ int s64[64];
    __shared__ int szc1[8];

    int acc = 0;
    #pragma unroll
    for (int b = 0; b < 8; ++b) {
        g_bb[p][b][c] = acc;
        acc += g_bh[p][b][c];
    }
    s64[c] = acc;
    __syncthreads();

    // prefix within c1 over the 8 sub-buckets
    int S = 0;
    const int c1 = c >> 3, c2p = c & 7;
    for (int j = 0; j < c2p; ++j) S += s64[(c1 << 3) + j];
    g_S[p][c] = S;

    if (c < 8) {
        int t = 0;
        for (int j = 0; j < 8; ++j) t += s64[(c << 3) + j];
        szc1[c] = t;
        g_szc1[p][c] = t;
    }
    __syncthreads();
    if (c == 0) {
        int ob = 0;
        for (int cc = 0; cc < 8; ++cc) {
            g_ovfb[p][cc] = ob;
            ob += max(0, szc1[cc] - SLOTS);
        }
    }
}

// ---------------- K3: ranks -> positions (48 blocks x 1024) ----------------
__global__ __launch_bounds__(1024) void k3_rank()
{
    const int p   = blockIdx.x >> 3;
    const int blk = blockIdx.x & 7;
    const int n   = (blk << 10) + threadIdx.x;
    const int wid = threadIdx.x >> 5;
    __shared__ int whist[32][64];

    const int cls = g_res[(size_t)p * WIDTH + n];
    const unsigned mask = __match_any_sync(0xffffffffu, cls);
    const int lrank = __popc(mask & ((1u << (threadIdx.x & 31)) - 1u));

    if (threadIdx.x < 2048 / 1) {           // zero warp hists
        // each thread zeros 2 entries: 32*64 = 2048 entries / 1024 threads
        ((int*)whist)[threadIdx.x]        = 0;
        ((int*)whist)[threadIdx.x + 1024] = 0;
    }
    __syncthreads();
    if ((__ffs(mask) - 1) == (int)(threadIdx.x & 31))
        whist[wid][cls] = __popc(mask);
    __syncthreads();

    int wbase = 0;
    for (int w = 0; w < wid; ++w) wbase += whist[w][cls];

    const int r64  = g_bb[p][blk][cls] + wbase + lrank;   // rank within 64-class
    const int kc1  = g_S[p][cls] + r64;                   // rank within c1 class
    const int c1   = cls >> 3;

    int pos;
    if (kc1 < SLOTS) {
        pos = (kc1 << 3) + c1;
    } else {
        int oidx = g_ovfb[p][c1] + (kc1 - SLOTS);
        pos = -1;
        for (int cc = 0; cc < 8; ++cc) {
            int nf = max(0, SLOTS - g_szc1[p][cc]);
            if (oidx < nf) { pos = ((g_szc1[p][cc] + oidx) << 3) + cc; break; }
            oidx -= nf;
        }
    }
    g_pos[(size_t)p * WIDTH + n] = pos;
    g_inv[(size_t)p * WIDTH + pos] = n;
}

// ---------------- K4: rewrite tables (remap + z/w swap greedy) -------------
__global__ __launch_bounds__(256) void k4_rewrite()
{
    const int idx = blockIdx.x * blockDim.x + threadIdx.x;   // 6*1024 octets
    const int p   = idx >> 10;
    const int j0  = (idx & 1023) << 3;
    const int* posPrev = g_pos + (size_t)(p - 1) * WIDTH;

    unsigned mask3 = 0;
    for (int e = 0; e < 8; ++e) {
        const int n = g_inv[(size_t)p * WIDTH + j0 + e];
        int4 t = g_fused[(size_t)p * WIDTH + n];
        if (p > 0) {
            t.x = __ldg(&posPrev[t.x]);
            t.y = __ldg(&posPrev[t.y]);
            t.z = __ldg(&posPrev[t.z]);
            t.w = __ldg(&posPrev[t.w]);
        }
        const int cz = t.z & 7, cw = t.w & 7;
        if (((mask3 >> cz) & 1u) && !((mask3 >> cw) & 1u)) {
            int tmp = t.z; t.z = t.w; t.w = tmp;
            mask3 |= 1u << cw;
        } else {
            mask3 |= 1u << cz;
        }
        g_fused2[(size_t)p * WIDTH + j0 + e] = t;
    }
}

// ---------------- main kernel (unchanged math, permuted tables) ------------
__device__ __forceinline__ u32 h2_as_u32(__half2 h) { u32 r; __builtin_memcpy(&r, &h, 4); return r; }
__device__ __forceinline__ __half2 u32_as_h2(u32 u) { __half2 h; __builtin_memcpy(&h, &u, 4); return h; }
__device__ __forceinline__ u32 fuse_u(u32 x1, u32 y1, u32 x2, u32 y2) {
    return h2_as_u32(__hfma2(u32_as_h2(x2), u32_as_h2(y2),
                             __hmul2(u32_as_h2(x1), u32_as_h2(y1))));
}
__device__ __forceinline__ uint4 gather_fuse(const uint4* __restrict__ buf, int4 t) {
    const uint4 x1 = buf[t.x];
    const uint4 y1 = buf[t.y];
    const uint4 x2 = buf[t.z];
    const uint4 y2 = buf[t.w];
    return make_uint4(fuse_u(x1.x, y1.x, x2.x, y2.x),
                      fuse_u(x1.y, y1.y, x2.y, y2.y),
                      fuse_u(x1.z, y1.z, x2.z, y2.z),
                      fuse_u(x1.w, y1.w, x2.w, y2.w));
}

__global__ __launch_bounds__(THREADS, 1) void wmc_kernel(
    const float* __restrict__ weights,
    const float* __restrict__ neg_weights,
    float* __restrict__ out)
{
    extern __shared__ uint4 buf[];          // 128 KB
    __shared__ float wsum[(THREADS / 32) * BCH];

    const int g   = blockIdx.x;
    const int tid = threadIdx.x;

    int4 t_pre[NPRE];
    #pragma unroll
    for (int k = 0; k < NPRE; ++k)
        t_pre[k] = __ldg(&g_fused2[tid + k * THREADS]);

    {
        const float* wb = weights     + (size_t)g * BCH * N_VARS;
        const float* nb = neg_weights + (size_t)g * BCH * N_VARS;
        for (int v = tid; v < N_VARS; v += THREADS) {
            __half2 w01 = __floats2half2_rn(__ldg(wb + v),            __ldg(wb + v + N_VARS));
            __half2 w23 = __floats2half2_rn(__ldg(wb + v + 2*N_VARS), __ldg(wb + v + 3*N_VARS));
            __half2 w45 = __floats2half2_rn(__ldg(wb + v + 4*N_VARS), __ldg(wb + v + 5*N_VARS));
            __half2 w67 = __floats2half2_rn(__ldg(wb + v + 6*N_VARS), __ldg(wb + v + 7*N_VARS));
            buf[v] = make_uint4(h2_as_u32(w01), h2_as_u32(w23), h2_as_u32(w45), h2_as_u32(w67));

            __half2 n01 = __floats2half2_rn(__ldg(nb + v),            __ldg(nb + v + N_VARS));
            __half2 n23 = __floats2half2_rn(__ldg(nb + v + 2*N_VARS), __ldg(nb + v + 3*N_VARS));
            __half2 n45 = __floats2half2_rn(__ldg(nb + v + 4*N_VARS), __ldg(nb + v + 5*N_VARS));
            __half2 n67 = __floats2half2_rn(__ldg(nb + v + 6*N_VARS), __ldg(nb + v + 7*N_VARS));
            buf[v + N_VARS] = make_uint4(h2_as_u32(n01), h2_as_u32(n23), h2_as_u32(n45), h2_as_u32(n67));
        }
    }
    __syncthreads();

    #pragma unroll
    for (int p = 0; p < N_PAIRS - 1; ++p) {
        const int4* __restrict__ ft  = g_fused2 + (size_t)p * WIDTH;
        const int4* __restrict__ ftn = g_fused2 + (size_t)(p + 1) * WIDTH;
        uint4 r[NPT];

        #pragma unroll
        for (int k = 0; k < NPRE; ++k)
            r[k] = gather_fuse(buf, t_pre[k]);
        #pragma unroll
        for (int k = NPRE; k < NPT; ++k)
            r[k] = gather_fuse(buf, __ldg(&ft[tid + k * THREADS]));

        __syncthreads();
        #pragma unroll
        for (int k = 0; k < NPT; ++k)
            buf[tid + k * THREADS] = r[k];
        #pragma unroll
        for (int k = 0; k < NPRE; ++k)
            t_pre[k] = __ldg(&ftn[tid + k * THREADS]);
        __syncthreads();
    }

    float acc[BCH];
    #pragma unroll
    for (int j = 0; j < BCH; ++j) acc[j] = 0.0f;
    {
        const int4* __restrict__ ft = g_fused2 + (size_t)(N_PAIRS - 1) * WIDTH;
        #pragma unroll
        for (int k = 0; k < NPT; ++k) {
            const int4 t = (k < NPRE) ? t_pre[k] : __ldg(&ft[tid + k * THREADS]);
            const uint4 rv = gather_fuse(buf, t);
            const u32 rs[4] = {rv.x, rv.y, rv.z, rv.w};
            #pragma unroll
            for (int q = 0; q < 4; ++q) {
                float2 f = __half22float2(u32_as_h2(rs[q]));
                acc[2*q + 0] += f.x;
                acc[2*q + 1] += f.y;
            }
        }
    }

    #pragma unroll
    for (int o = 16; o > 0; o >>= 1) {
        #pragma unroll
        for (int j = 0; j < BCH; ++j)
            acc[j] += __shfl_xor_sync(0xffffffffu, acc[j], o);
    }
    if ((tid & 31) == 0) {
        #pragma unroll
        for (int j = 0; j < BCH; ++j)
            wsum[(tid >> 5) * BCH + j] = acc[j];
    }
    __syncthreads();

    if (tid < 32) {
        #pragma unroll
        for (int j = 0; j < BCH; ++j) {
            float s = wsum[tid * BCH + j];
            #pragma unroll
            for (int o = 16; o > 0; o >>= 1)
                s += __shfl_xor_sync(0xffffffffu, s, o);
            if (tid == 0) out[g * BCH + j] = s;
        }
    }
}

extern "C" void kernel_launch(void* const* d_in, const int* in_sizes, int n_in,
                              void* d_out, int out_size)
{
    const float* weights     = (const float*)d_in[0];
    const float* neg_weights = (const float*)d_in[1];
    const int2*  children    = (const int2*)d_in[2];
    float* out = (float*)d_out;

    k1_fuse_res<<<N_PAIRS * 8, 1024>>>(children);
    k2_scan   <<<N_PAIRS, 64>>>();
    k3_rank   <<<N_PAIRS * 8, 1024>>>();
    k4_rewrite<<<(N_PAIRS * 1024) / 256, 256>>>();

    const int smem_bytes = WIDTH * sizeof(uint4);
    cudaFuncSetAttribute(wmc_kernel, cudaFuncAttributeMaxDynamicSharedMemorySize, smem_bytes);
    wmc_kernel<<<BATCH / BCH, THREADS, smem_bytes>>>(weights, neg_weights, out);
}

// round 9
// speedup vs baseline: 1.1008x; 1.1008x over previous
#include <cuda_runtime.h>
#include <cuda_fp16.h>
#include <cstddef>
#include <cstdint>

#define N_VARS   4096
#define WIDTH    8192
#define N_LAYERS 12
#define BATCH    1024
#define THREADS  1024
#define BCH      8
#define NPT      (WIDTH / THREADS)          // 8
#define NPRE     4
#define N_PAIRS  (N_LAYERS / 2)             // 6 fused stages
#define N_PERM   (N_PAIRS - 1)              // stages 0..4 get permuted outputs
#define SLOTS    (WIDTH / 8)                // 1024 positions per residue class

typedef unsigned int u32;

// ---------------- device-global scratch (sanctioned) ----------------
__device__ int4 g_fused [N_PAIRS * WIDTH];
__device__ int4 g_fused2[N_PAIRS * WIDTH];
__device__ int  g_res  [N_PAIRS * WIDTH];
__device__ int  g_bh   [N_PERM][8][64];
__device__ int  g_bb   [N_PERM][8][64];
__device__ int  g_S    [N_PERM][64];
__device__ int  g_szc1 [N_PERM][8];
__device__ int  g_ovfb [N_PERM][8];
__device__ int  g_pos  [N_PERM * WIDTH];    // node -> position (stages 0..4)
__device__ int  g_inv  [N_PERM * WIDTH];    // position -> node

// ---------------- K1: fused tables + residue classes + block hist ----------
__global__ __launch_bounds__(1024) void k1_fuse_res(const int2* __restrict__ ch)
{
    const int p = blockIdx.x >> 3;
    const int n = ((blockIdx.x & 7) << 10) + threadIdx.x;
    __shared__ int hist[64];
    if (threadIdx.x < 64) hist[threadIdx.x] = 0;
    __syncthreads();

    const int2 s = __ldg(&ch[(size_t)(2 * p + 1) * WIDTH + n]);
    const int2 a = __ldg(&ch[(size_t)(2 * p) * WIDTH + s.x]);
    const int2 b = __ldg(&ch[(size_t)(2 * p) * WIDTH + s.y]);
    g_fused[(size_t)p * WIDTH + n] = make_int4(a.x, a.y, b.x, b.y);

    if (p < N_PERM) {
        // c1: chain first children down to the (identity) input layer
        int r = n;
        for (int q = p; q >= 0; --q) {
            int sx = __ldg(&ch[(size_t)(2 * q + 1) * WIDTH + r]).x;
            r = __ldg(&ch[(size_t)(2 * q) * WIDTH + sx]).x;
        }
        const int c1 = r & 7;

        // c2: second gather target (a.y), then first-child chains below
        int r2 = a.y;
        for (int q = p - 1; q >= 0; --q) {
            int sx = __ldg(&ch[(size_t)(2 * q + 1) * WIDTH + r2]).x;
            r2 = __ldg(&ch[(size_t)(2 * q) * WIDTH + sx]).x;
        }
        const int c2 = r2 & 7;

        const int cls = (c1 << 3) | ((c2 - c1) & 7);
        g_res[(size_t)p * WIDTH + n] = cls;

        unsigned mask = __match_any_sync(0xffffffffu, cls);
        if ((__ffs(mask) - 1) == (int)(threadIdx.x & 31))
            atomicAdd(&hist[cls], __popc(mask));
    }
    __syncthreads();
    if (p < N_PERM && threadIdx.x < 64)
        g_bh[p][blockIdx.x & 7][threadIdx.x] = hist[threadIdx.x];
}

// ---------------- K2: per-stage scans (5 blocks x 64) ----------------------
__global__ __launch_bounds__(64) void k2_scan()
{
    const int p = blockIdx.x;
    const int c = threadIdx.x;
    __shared__ int s64[64];
    __shared__ int szc1[8];

    int acc = 0;
    #pragma unroll
    for (int b = 0; b < 8; ++b) {
        g_bb[p][b][c] = acc;
        acc += g_bh[p][b][c];
    }
    s64[c] = acc;
    __syncthreads();

    int S = 0;
    const int c1 = c >> 3, c2p = c & 7;
    for (int j = 0; j < c2p; ++j) S += s64[(c1 << 3) + j];
    g_S[p][c] = S;

    if (c < 8) {
        int t = 0;
        for (int j = 0; j < 8; ++j) t += s64[(c << 3) + j];
        szc1[c] = t;
        g_szc1[p][c] = t;
    }
    __syncthreads();
    if (c == 0) {
        int ob = 0;
        for (int cc = 0; cc < 8; ++cc) {
            g_ovfb[p][cc] = ob;
            ob += max(0, szc1[cc] - SLOTS);
        }
    }
}

// ---------------- K3: ranks -> positions (40 blocks x 1024) ----------------
__global__ __launch_bounds__(1024) void k3_rank()
{
    const int p   = blockIdx.x >> 3;
    const int blk = blockIdx.x & 7;
    const int n   = (blk << 10) + threadIdx.x;
    const int wid = threadIdx.x >> 5;
    __shared__ int whist[32][64];

    const int cls = g_res[(size_t)p * WIDTH + n];
    const unsigned mask = __match_any_sync(0xffffffffu, cls);
    const int lrank = __popc(mask & ((1u << (threadIdx.x & 31)) - 1u));

    ((int*)whist)[threadIdx.x]        = 0;
    ((int*)whist)[threadIdx.x + 1024] = 0;
    __syncthreads();
    if ((__ffs(mask) - 1) == (int)(threadIdx.x & 31))
        whist[wid][cls] = __popc(mask);
    __syncthreads();

    int wbase = 0;
    for (int w = 0; w < wid; ++w) wbase += whist[w][cls];

    const int r64 = g_bb[p][blk][cls] + wbase + lrank;
    const int kc1 = g_S[p][cls] + r64;
    const int c1  = cls >> 3;

    int pos;
    if (kc1 < SLOTS) {
        pos = (kc1 << 3) + c1;
    } else {
        int oidx = g_ovfb[p][c1] + (kc1 - SLOTS);
        pos = 0;
        for (int cc = 0; cc < 8; ++cc) {
            int nf = max(0, SLOTS - g_szc1[p][cc]);
            if (oidx < nf) { pos = ((g_szc1[p][cc] + oidx) << 3) + cc; break; }
            oidx -= nf;
        }
    }
    g_pos[(size_t)p * WIDTH + n] = pos;
    g_inv[(size_t)p * WIDTH + pos] = n;
}

// ---------------- K4: rewrite tables, 1 thread/element, shfl greedy --------
__global__ __launch_bounds__(1024) void k4_rewrite()
{
    const int idx   = blockIdx.x * 1024 + threadIdx.x;   // 6*8192 elements
    const int p     = idx >> 13;
    const int j     = idx & (WIDTH - 1);
    const int lane8 = threadIdx.x & 7;

    const int n = (p < N_PERM) ? g_inv[(size_t)p * WIDTH + j] : j;
    int4 t = g_fused[(size_t)p * WIDTH + n];
    if (p > 0) {
        const int* posPrev = g_pos + (size_t)(p - 1) * WIDTH;
        t.x = __ldg(&posPrev[t.x]);
        t.y = __ldg(&posPrev[t.y]);
        t.z = __ldg(&posPrev[t.z]);
        t.w = __ldg(&posPrev[t.w]);
    }

    // greedy z/w swap across the 8 lanes of this octet (deterministic)
    unsigned mask3 = 0;
    const int cz = t.z & 7, cw = t.w & 7;
    #pragma unroll
    for (int e = 0; e < 8; ++e) {
        const int czb = __shfl_sync(0xffffffffu, cz, e, 8);
        const int cwb = __shfl_sync(0xffffffffu, cw, e, 8);
        const bool sw = ((mask3 >> czb) & 1u) && !((mask3 >> cwb) & 1u);
        mask3 |= 1u << (sw ? cwb : czb);
        if (lane8 == e && sw) { const int tmp = t.z; t.z = t.w; t.w = tmp; }
    }
    g_fused2[(size_t)p * WIDTH + j] = t;
}

// ---------------- main kernel ----------------------------------------------
__device__ __forceinline__ u32 h2_as_u32(__half2 h) { u32 r; __builtin_memcpy(&r, &h, 4); return r; }
__device__ __forceinline__ __half2 u32_as_h2(u32 u) { __half2 h; __builtin_memcpy(&h, &u, 4); return h; }
__device__ __forceinline__ u32 fuse_u(u32 x1, u32 y1, u32 x2, u32 y2) {
    return h2_as_u32(__hfma2(u32_as_h2(x2), u32_as_h2(y2),
                             __hmul2(u32_as_h2(x1), u32_as_h2(y1))));
}
__device__ __forceinline__ uint4 gather_fuse(const uint4* __restrict__ buf, int4 t) {
    const uint4 x1 = buf[t.x];
    const uint4 y1 = buf[t.y];
    const uint4 x2 = buf[t.z];
    const uint4 y2 = buf[t.w];
    return make_uint4(fuse_u(x1.x, y1.x, x2.x, y2.x),
                      fuse_u(x1.y, y1.y, x2.y, y2.y),
                      fuse_u(x1.z, y1.z, x2.z, y2.z),
                      fuse_u(x1.w, y1.w, x2.w, y2.w));
}

__global__ __launch_bounds__(THREADS, 1) void wmc_kernel(
    const float* __restrict__ weights,
    const float* __restrict__ neg_weights,
    float* __restrict__ out)
{
    extern __shared__ uint4 buf[];          // 128 KB
    __shared__ float wsum[(THREADS / 32) * BCH];

    const int g   = blockIdx.x;
    const int tid = threadIdx.x;

    int4 t_pre[NPRE];
    #pragma unroll
    for (int k = 0; k < NPRE; ++k)
        t_pre[k] = __ldg(&g_fused2[tid + k * THREADS]);

    {
        const float* wb = weights     + (size_t)g * BCH * N_VARS;
        const float* nb = neg_weights + (size_t)g * BCH * N_VARS;
        for (int v = tid; v < N_VARS; v += THREADS) {
            __half2 w01 = __floats2half2_rn(__ldg(wb + v),            __ldg(wb + v + N_VARS));
            __half2 w23 = __floats2half2_rn(__ldg(wb + v + 2*N_VARS), __ldg(wb + v + 3*N_VARS));
            __half2 w45 = __floats2half2_rn(__ldg(wb + v + 4*N_VARS), __ldg(wb + v + 5*N_VARS));
            __half2 w67 = __floats2half2_rn(__ldg(wb + v + 6*N_VARS), __ldg(wb + v + 7*N_VARS));
            buf[v] = make_uint4(h2_as_u32(w01), h2_as_u32(w23), h2_as_u32(w45), h2_as_u32(w67));

            __half2 n01 = __floats2half2_rn(__ldg(nb + v),            __ldg(nb + v + N_VARS));
            __half2 n23 = __floats2half2_rn(__ldg(nb + v + 2*N_VARS), __ldg(nb + v + 3*N_VARS));
            __half2 n45 = __floats2half2_rn(__ldg(nb + v + 4*N_VARS), __ldg(nb + v + 5*N_VARS));
            __half2 n67 = __floats2half2_rn(__ldg(nb + v + 6*N_VARS), __ldg(nb + v + 7*N_VARS));
            buf[v + N_VARS] = make_uint4(h2_as_u32(n01), h2_as_u32(n23), h2_as_u32(n45), h2_as_u32(n67));
        }
    }
    __syncthreads();

    #pragma unroll
    for (int p = 0; p < N_PAIRS - 1; ++p) {
        const int4* __restrict__ ft  = g_fused2 + (size_t)p * WIDTH;
        const int4* __restrict__ ftn = g_fused2 + (size_t)(p + 1) * WIDTH;
        uint4 r[NPT];

        #pragma unroll
        for (int k = 0; k < NPRE; ++k)
            r[k] = gather_fuse(buf, t_pre[k]);
        #pragma unroll
        for (int k = NPRE; k < NPT; ++k)
            r[k] = gather_fuse(buf, __ldg(&ft[tid + k * THREADS]));

        __syncthreads();
        #pragma unroll
        for (int k = 0; k < NPT; ++k)
            buf[tid + k * THREADS] = r[k];
        #pragma unroll
        for (int k = 0; k < NPRE; ++k)
            t_pre[k] = __ldg(&ftn[tid + k * THREADS]);
        __syncthreads();
    }

    float acc[BCH];
    #pragma unroll
    for (int j = 0; j < BCH; ++j) acc[j] = 0.0f;
    {
        const int4* __restrict__ ft = g_fused2 + (size_t)(N_PAIRS - 1) * WIDTH;
        #pragma unroll
        for (int k = 0; k < NPT; ++k) {
            const int4 t = (k < NPRE) ? t_pre[k] : __ldg(&ft[tid + k * THREADS]);
            const uint4 rv = gather_fuse(buf, t);
            const u32 rs[4] = {rv.x, rv.y, rv.z, rv.w};
            #pragma unroll
            for (int q = 0; q < 4; ++q) {
                float2 f = __half22float2(u32_as_h2(rs[q]));
                acc[2*q + 0] += f.x;
                acc[2*q + 1] += f.y;
            }
        }
    }

    #pragma unroll
    for (int o = 16; o > 0; o >>= 1) {
        #pragma unroll
        for (int j = 0; j < BCH; ++j)
            acc[j] += __shfl_xor_sync(0xffffffffu, acc[j], o);
    }
    if ((tid & 31) == 0) {
        #pragma unroll
        for (int j = 0; j < BCH; ++j)
            wsum[(tid >> 5) * BCH + j] = acc[j];
    }
    __syncthreads();

    if (tid < 32) {
        #pragma unroll
        for (int j = 0; j < BCH; ++j) {
            float s = wsum[tid * BCH + j];
            #pragma unroll
            for (int o = 16; o > 0; o >>= 1)
                s += __shfl_xor_sync(0xffffffffu, s, o);
            if (tid == 0) out[g * BCH + j] = s;
        }
    }
}

extern "C" void kernel_launch(void* const* d_in, const int* in_sizes, int n_in,
                              void* d_out, int out_size)
{
    const float* weights     = (const float*)d_in[0];
    const float* neg_weights = (const float*)d_in[1];
    const int2*  children    = (const int2*)d_in[2];
    float* out = (float*)d_out;

    k1_fuse_res<<<N_PAIRS * 8, 1024>>>(children);
    k2_scan   <<<N_PERM, 64>>>();
    k3_rank   <<<N_PERM * 8, 1024>>>();
    k4_rewrite<<<(N_PAIRS * WIDTH) / 1024, 1024>>>();

    const int smem_bytes = WIDTH * sizeof(uint4);
    cudaFuncSetAttribute(wmc_kernel, cudaFuncAttributeMaxDynamicSharedMemorySize, smem_bytes);
    wmc_kernel<<<BATCH / BCH, THREADS, smem_bytes>>>(weights, neg_weights, out);
}

// round 10
// speedup vs baseline: 1.3298x; 1.2080x over previous
#include <cuda_runtime.h>
#include <cuda_fp16.h>
#include <cstddef>
#include <cstdint>

#define N_VARS   4096
#define WIDTH    8192
#define N_LAYERS 12
#define BATCH    1024
#define THREADS  1024
#define BCH      8
#define NPT      (WIDTH / THREADS)          // 8
#define NPRE     4                          // k=0..3 via register prefetch
#define N_PAIRS  (N_LAYERS / 2)             // 6 fused stages

typedef unsigned int u32;

// Fused index tables: for pair p, node i:
//   s = children[2p+1][i];  (A,B) = children[2p][s.x];  (C,D) = children[2p][s.y]
__device__ int4 g_fused[N_PAIRS * WIDTH];

__global__ __launch_bounds__(256) void prep_kernel(const int2* __restrict__ children)
{
    const int idx = blockIdx.x * blockDim.x + threadIdx.x;
    const int p = idx >> 13;
    const int i = idx & (WIDTH - 1);
    const int2* ch_even = children + (size_t)(2 * p) * WIDTH;
    const int2 s = __ldg(&children[(size_t)(2 * p + 1) * WIDTH + i]);
    const int2 a = __ldg(&ch_even[s.x]);
    const int2 b = __ldg(&ch_even[s.y]);
    g_fused[idx] = make_int4(a.x, a.y, b.x, b.y);
}

__device__ __forceinline__ u32 h2_as_u32(__half2 h) { u32 r; __builtin_memcpy(&r, &h, 4); return r; }
__device__ __forceinline__ __half2 u32_as_h2(u32 u) { __half2 h; __builtin_memcpy(&h, &u, 4); return h; }
__device__ __forceinline__ u32 fuse_u(u32 x1, u32 y1, u32 x2, u32 y2) {
    return h2_as_u32(__hfma2(u32_as_h2(x2), u32_as_h2(y2),
                             __hmul2(u32_as_h2(x1), u32_as_h2(y1))));
}
__device__ __forceinline__ uint4 gather_fuse(const uint4* __restrict__ buf, int4 t) {
    const uint4 x1 = buf[t.x];
    const uint4 y1 = buf[t.y];
    const uint4 x2 = buf[t.z];
    const uint4 y2 = buf[t.w];
    return make_uint4(fuse_u(x1.x, y1.x, x2.x, y2.x),
                      fuse_u(x1.y, y1.y, x2.y, y2.y),
                      fuse_u(x1.z, y1.z, x2.z, y2.z),
                      fuse_u(x1.w, y1.w, x2.w, y2.w));
}

__device__ __forceinline__ void cp_async16(u32 smem_addr, const void* gptr) {
    asm volatile("cp.async.cg.shared.global [%0], [%1], 16;"
                 :: "r"(smem_addr), "l"(gptr) : "memory");
}
__device__ __forceinline__ void cp_async_commit() {
    asm volatile("cp.async.commit_group;" ::: "memory");
}
__device__ __forceinline__ void cp_async_wait0() {
    asm volatile("cp.async.wait_group 0;" ::: "memory");
}

// One CTA (32 warps) per 8 batch rows; vals node-major as 8 halves (uint4) in
// 128KB SMEM; 6 fused product->sum stages. Table access is fully off the
// critical path: k=0..3 entries prefetched to registers across the barrier,
// k=4..7 entries staged into 64KB SMEM via cp.async during the store phase.
__global__ __launch_bounds__(THREADS, 1) void wmc_kernel(
    const float* __restrict__ weights,
    const float* __restrict__ neg_weights,
    float* __restrict__ out)
{
    extern __shared__ uint4 smem[];
    uint4* buf = smem;                      // [WIDTH]           128 KB
    int4*  tsm = (int4*)(smem + WIDTH);     // [4*THREADS]        64 KB
    __shared__ float wsum[(THREADS / 32) * BCH];

    const int g   = blockIdx.x;
    const int tid = threadIdx.x;
    const u32 tsm_base = (u32)__cvta_generic_to_shared(tsm);

    // ---- Stage-0 table prefetch: lo half -> regs, hi half -> smem ----
    int4 t_pre[NPRE];
    #pragma unroll
    for (int k = 0; k < NPRE; ++k)
        t_pre[k] = __ldg(&g_fused[tid + k * THREADS]);
    #pragma unroll
    for (int k = NPRE; k < NPT; ++k)
        cp_async16(tsm_base + (u32)(tid + (k - NPRE) * THREADS) * 16u,
                   &g_fused[tid + k * THREADS]);
    cp_async_commit();

    // ---- Load + transpose 8 rows of (weights ‖ neg_weights), fp32 -> fp16 ----
    {
        const float* wb = weights     + (size_t)g * BCH * N_VARS;
        const float* nb = neg_weights + (size_t)g * BCH * N_VARS;
        for (int v = tid; v < N_VARS; v += THREADS) {
            __half2 w01 = __floats2half2_rn(__ldg(wb + v),            __ldg(wb + v + N_VARS));
            __half2 w23 = __floats2half2_rn(__ldg(wb + v + 2*N_VARS), __ldg(wb + v + 3*N_VARS));
            __half2 w45 = __floats2half2_rn(__ldg(wb + v + 4*N_VARS), __ldg(wb + v + 5*N_VARS));
            __half2 w67 = __floats2half2_rn(__ldg(wb + v + 6*N_VARS), __ldg(wb + v + 7*N_VARS));
            buf[v] = make_uint4(h2_as_u32(w01), h2_as_u32(w23), h2_as_u32(w45), h2_as_u32(w67));

            __half2 n01 = __floats2half2_rn(__ldg(nb + v),            __ldg(nb + v + N_VARS));
            __half2 n23 = __floats2half2_rn(__ldg(nb + v + 2*N_VARS), __ldg(nb + v + 3*N_VARS));
            __half2 n45 = __floats2half2_rn(__ldg(nb + v + 4*N_VARS), __ldg(nb + v + 5*N_VARS));
            __half2 n67 = __floats2half2_rn(__ldg(nb + v + 6*N_VARS), __ldg(nb + v + 7*N_VARS));
            buf[v + N_VARS] = make_uint4(h2_as_u32(n01), h2_as_u32(n23), h2_as_u32(n45), h2_as_u32(n67));
        }
    }
    __syncthreads();

    // ---- Stages 0..4: fused (product, sum) layer pairs, in place ----
    #pragma unroll
    for (int p = 0; p < N_PAIRS - 1; ++p) {
        const int4* __restrict__ ftn = g_fused + (size_t)(p + 1) * WIDTH;
        uint4 r[NPT];

        #pragma unroll
        for (int k = 0; k < NPRE; ++k)
            r[k] = gather_fuse(buf, t_pre[k]);
        cp_async_wait0();                       // own hi-half entries are ready
        #pragma unroll
        for (int k = NPRE; k < NPT; ++k)
            r[k] = gather_fuse(buf, tsm[tid + (k - NPRE) * THREADS]);

        __syncthreads();                        // all gathers done
        #pragma unroll
        for (int k = 0; k < NPT; ++k)
            buf[tid + k * THREADS] = r[k];
        // next-stage table prefetch: latency drains under stores + barrier
        #pragma unroll
        for (int k = NPRE; k < NPT; ++k)
            cp_async16(tsm_base + (u32)(tid + (k - NPRE) * THREADS) * 16u,
                       &ftn[tid + k * THREADS]);
        cp_async_commit();
        #pragma unroll
        for (int k = 0; k < NPRE; ++k)
            t_pre[k] = __ldg(&ftn[tid + k * THREADS]);
        __syncthreads();                        // all stores visible
    }

    // ---- Stage 5 (layers 10+11): fold into fp32 reduction ----
    float acc[BCH];
    #pragma unroll
    for (int j = 0; j < BCH; ++j) acc[j] = 0.0f;
    {
        #pragma unroll
        for (int k = 0; k < NPRE; ++k) {
            const uint4 rv = gather_fuse(buf, t_pre[k]);
            const u32 rs[4] = {rv.x, rv.y, rv.z, rv.w};
            #pragma unroll
            for (int q = 0; q < 4; ++q) {
                float2 f = __half22float2(u32_as_h2(rs[q]));
                acc[2*q + 0] += f.x;
                acc[2*q + 1] += f.y;
            }
        }
        cp_async_wait0();
        #pragma unroll
        for (int k = NPRE; k < NPT; ++k) {
            const uint4 rv = gather_fuse(buf, tsm[tid + (k - NPRE) * THREADS]);
            const u32 rs[4] = {rv.x, rv.y, rv.z, rv.w};
            #pragma unroll
            for (int q = 0; q < 4; ++q) {
                float2 f = __half22float2(u32_as_h2(rs[q]));
                acc[2*q + 0] += f.x;
                acc[2*q + 1] += f.y;
            }
        }
    }

    // ---- CTA-wide reduction of 8 fp32 accumulators ----
    #pragma unroll
    for (int o = 16; o > 0; o >>= 1) {
        #pragma unroll
        for (int j = 0; j < BCH; ++j)
            acc[j] += __shfl_xor_sync(0xffffffffu, acc[j], o);
    }
    if ((tid & 31) == 0) {
        #pragma unroll
        for (int j = 0; j < BCH; ++j)
            wsum[(tid >> 5) * BCH + j] = acc[j];
    }
    __syncthreads();

    if (tid < 32) {
        #pragma unroll
        for (int j = 0; j < BCH; ++j) {
            float s = wsum[tid * BCH + j];
            #pragma unroll
            for (int o = 16; o > 0; o >>= 1)
                s += __shfl_xor_sync(0xffffffffu, s, o);
            if (tid == 0) out[g * BCH + j] = s;
        }
    }
}

extern "C" void kernel_launch(void* const* d_in, const int* in_sizes, int n_in,
                              void* d_out, int out_size)
{
    const float* weights     = (const float*)d_in[0];
    const float* neg_weights = (const float*)d_in[1];
    const int2*  children    = (const int2*)d_in[2];
    float* out = (float*)d_out;

    prep_kernel<<<(N_PAIRS * WIDTH) / 256, 256>>>(children);

    const int smem_bytes = WIDTH * sizeof(uint4) + 4 * THREADS * sizeof(int4);  // 192 KB
    cudaFuncSetAttribute(wmc_kernel, cudaFuncAttributeMaxDynamicSharedMemorySize, smem_bytes);
    wmc_kernel<<<BATCH / BCH, THREADS, smem_bytes>>>(weights, neg_weights, out);
}